// round 14
// baseline (speedup 1.0000x reference)
#include <cuda_runtime.h>
#include <cuda_fp16.h>
#include <cstdint>

#define N 8192
#define D 64
#define E 262144

// Scratch (no allocations allowed — __device__ globals)
__device__ float  g_sk[N * D];    // normalized state_K (fp32)
__device__ __half g_skh[N * D];   // normalized state_K (fp16, for edge gathers)
__device__ float  g_g[N];         // tanh(state_H)
__device__ float  g_fk[N * D];    // f_K accumulator (pre-projection)
__device__ float  g_zt[N];        // 0.5 * W_hop^T @ g accumulator
__device__ float  g_om[D * D];    // antisymmetrized (omega - omega^T)/2, ONCE

__device__ __forceinline__ void red_add_v4(float* p, float4 v) {
    asm volatile("red.global.add.v4.f32 [%0], {%1,%2,%3,%4};"
                 :: "l"(p), "f"(v.x), "f"(v.y), "f"(v.z), "f"(v.w)
                 : "memory");
}

// ---------------------------------------------------------------------------
// prep: sk = normalize(state_K rows) (fp32 + fp16), g = tanh(state_H),
//       zero accumulators, out_fH = -state_H.
//       Block 0 antisymmetrizes omega into g_om (transposed read paid ONCE).
// grid 1024 x 256 : one warp per row of state_K.
// ---------------------------------------------------------------------------
__global__ void __launch_bounds__(256) prep_kernel(
    const float* __restrict__ stateH,
    const float* __restrict__ stateK,
    const float* __restrict__ omega,
    float* __restrict__ outH)
{
    int tid  = threadIdx.x;
    int gtid = blockIdx.x * 256 + tid;

    ((float2*)g_fk)[gtid] = make_float2(0.f, 0.f);

    if (blockIdx.x == 0) {
        #pragma unroll
        for (int t = tid; t < D * D; t += 256) {
            int d = t >> 6, c = t & 63;
            g_om[t] = 0.5f * (omega[t] - omega[c * D + d]);
        }
    }

    int row  = gtid >> 5;
    int lane = tid & 31;
    float2 v = ((const float2*)(stateK + (size_t)row * D))[lane];
    float ss = v.x * v.x + v.y * v.y;
    #pragma unroll
    for (int o = 16; o; o >>= 1) ss += __shfl_xor_sync(0xffffffffu, ss, o);
    float inv = rsqrtf(ss);
    float2 s2 = make_float2(v.x * inv, v.y * inv);
    ((float2*)(g_sk + (size_t)row * D))[lane] = s2;
    ((__half2*)(g_skh + (size_t)row * D))[lane] = __float22half2_rn(s2);

    if (gtid < N) {
        float h = stateH[gtid];
        g_g[gtid]  = tanhf(h);
        g_zt[gtid] = 0.f;
        outH[gtid] = -h;
    }
}

// ---------------------------------------------------------------------------
// matvec: single pass over W_hop (256 MB) computing BOTH W@g and W^T@g.
// grid 256 x 256, 32 rows/block — HALF the co-resident blocks of before, so
// the concurrent edge kernel keeps its occupancy; DRAM saturation preserved
// (~2 waves, ample MLP). g_zt flush traffic also halves.
// ---------------------------------------------------------------------------
#define MV_ROWS 32

__global__ void __launch_bounds__(256) matvec_kernel(
    const float* __restrict__ W,
    float* __restrict__ outH)
{
    __shared__ float4 gsh[N / 4];
    int tid = threadIdx.x;
    #pragma unroll
    for (int k = 0; k < 8; k++)
        gsh[tid + 256 * k] = ((const float4*)g_g)[tid + 256 * k];
    __syncthreads();
    const float* gs = (const float*)gsh;

    float4 va[8];
    #pragma unroll
    for (int k = 0; k < 8; k++) va[k] = make_float4(0.f, 0.f, 0.f, 0.f);

    int r0 = blockIdx.x * MV_ROWS;
    for (int r = 0; r < MV_ROWS; r++) {
        const float4* rowp = (const float4*)(W + (size_t)(r0 + r) * N);
        float gr = gs[r0 + r];
        float dp = 0.f;
        #pragma unroll
        for (int k = 0; k < 8; k++) {
            float4 w  = __ldcs(&rowp[tid + 256 * k]);   // streaming, evict-first
            float4 gv = gsh[tid + 256 * k];
            dp = fmaf(w.x, gv.x, dp); dp = fmaf(w.y, gv.y, dp);
            dp = fmaf(w.z, gv.z, dp); dp = fmaf(w.w, gv.w, dp);
            va[k].x = fmaf(w.x, gr, va[k].x);
            va[k].y = fmaf(w.y, gr, va[k].y);
            va[k].z = fmaf(w.z, gr, va[k].z);
            va[k].w = fmaf(w.w, gr, va[k].w);
        }
        #pragma unroll
        for (int o = 16; o; o >>= 1) dp += __shfl_xor_sync(0xffffffffu, dp, o);
        if ((tid & 31) == 0) atomicAdd(&outH[r0 + r], 0.5f * dp);
    }
    #pragma unroll
    for (int k = 0; k < 8; k++) {
        int i4 = tid + 256 * k;
        red_add_v4(g_zt + 4 * i4,
                   make_float4(0.5f * va[k].x, 0.5f * va[k].y,
                               0.5f * va[k].z, 0.5f * va[k].w));
    }
}

// ---------------------------------------------------------------------------
// edges: both lists fused. Half-warp (16 lanes) per edge; fp16 sk gathers,
// fp32 math + red.v4 scatter. Measured 58.5us solo (LSU/REDG floor) —
// occupancy-sensitive, so it gets the HIGH-PRIORITY stream.
// grid 32768 x 256 (16 edges per block).
// ---------------------------------------------------------------------------
__global__ void __launch_bounds__(256) edge_kernel(
    const int* __restrict__ indK,
    const int* __restrict__ indHK,
    const float* __restrict__ W,
    const float* __restrict__ coeffs,
    const float* __restrict__ kKp,
    const float* __restrict__ kHp,
    float* __restrict__ outH)
{
    int gtid = blockIdx.x * 256 + threadIdx.x;
    int edge = gtid >> 4;               // half-warp id = edge id, [0, 2E)
    int l    = threadIdx.x & 15;

    bool isK = edge < E;
    int e2   = isK ? edge : edge - E;
    const int* ind = isK ? indK : indHK;
    int2 ij = ((const int2*)ind)[e2];
    int i = ij.x, j = ij.y;

    uint2 hi2 = ((const uint2*)(g_skh + (size_t)i * D))[l];
    uint2 hj2 = ((const uint2*)(g_skh + (size_t)j * D))[l];
    float2 a0 = __half22float2(*(const __half2*)&hi2.x);
    float2 a1 = __half22float2(*(const __half2*)&hi2.y);
    float2 b0 = __half22float2(*(const __half2*)&hj2.x);
    float2 b1 = __half22float2(*(const __half2*)&hj2.y);
    float4 si = make_float4(a0.x, a0.y, a1.x, a1.y);
    float4 sj = make_float4(b0.x, b0.y, b1.x, b1.y);

    float dp = si.x * sj.x + si.y * sj.y + si.z * sj.z + si.w * sj.w;
    #pragma unroll
    for (int o = 8; o; o >>= 1) dp += __shfl_xor_sync(0xffffffffu, dp, o, 16);

    float coef;
    if (isK) {
        float c0 = coeffs[0], c1 = coeffs[1], c2 = coeffs[2], c3 = coeffs[3];
        coef = dp * (c0 + dp * (c1 + dp * (c2 + dp * c3)));
    } else {
        float wij = 0.5f * (W[(size_t)i * N + j] + W[(size_t)j * N + i]);
        float gi = g_g[i], gj = g_g[j];
        if (l == 0) {
            float ikH = 1.f / *kHp;
            atomicAdd(&outH[i], dp * wij * gj * ikH);
            atomicAdd(&outH[j], dp * wij * gi * ikH);
        }
        coef = -gi * gj * wij / *kKp;
    }

    red_add_v4(g_fk + (size_t)i * D + 4 * l,
               make_float4(coef * sj.x, coef * sj.y, coef * sj.z, coef * sj.w));
    red_add_v4(g_fk + (size_t)j * D + 4 * l,
               make_float4(coef * si.x, coef * si.y, coef * si.z, coef * si.w));
}

// ---------------------------------------------------------------------------
// final: streaming combine + rotation (11.3us measured).
// grid 1024 x 256 (8 rows/block).
// ---------------------------------------------------------------------------
__global__ void __launch_bounds__(256, 3) final_kernel(float* __restrict__ out)
{
    __shared__ float Om[D * D];
    int tid  = threadIdx.x;
    int w    = tid >> 5;
    int lane = tid & 31;
    int r    = blockIdx.x * 8 + w;

    float2 raw = ((const float2*)(g_fk + (size_t)r * D))[lane];
    float2 skr = ((const float2*)(g_sk + (size_t)r * D))[lane];

    #pragma unroll
    for (int t = tid; t < D * D; t += 256)
        Om[t] = g_om[t];

    if (tid < 8) {
        int hidx = blockIdx.x * 8 + tid;
        out[hidx] += g_zt[hidx];
    }
    __syncthreads();

    float dp = skr.x * raw.x + skr.y * raw.y;
    #pragma unroll
    for (int o = 16; o; o >>= 1) dp += __shfl_xor_sync(0xffffffffu, dp, o);

    const float2* Om2 = (const float2*)Om;
    float ax = 0.f, ay = 0.f;
    #pragma unroll
    for (int dd = 0; dd < D; dd += 8) {
        float2 om[8];
        #pragma unroll
        for (int q = 0; q < 8; q++)
            om[q] = Om2[(dd + q) * 32 + lane];          // conflict-free LDS.64
        #pragma unroll
        for (int q = 0; q < 8; q++) {
            int d = dd + q;
            float s = __shfl_sync(0xffffffffu, (d & 1) ? skr.y : skr.x, d >> 1);
            ax = fmaf(s, om[q].x, ax);
            ay = fmaf(s, om[q].y, ay);
        }
    }

    float2 o2;
    o2.x = -raw.x + skr.x * dp + ax;
    o2.y = -raw.y + skr.y * dp + ay;
    ((float2*)(out + N))[r * 32 + lane] = o2;
}

// ---------------------------------------------------------------------------
// Launch graph:  prep ──┬── edge   (HIGH-priority side stream) ──┬── final
//                       └── matvec (default stream, 256 blocks) ─┘
// edge is the long pole and occupancy-sensitive → priority + launched first.
// matvec only needs MLP to saturate DRAM → fine with leftover slots.
// ---------------------------------------------------------------------------
extern "C" void kernel_launch(void* const* d_in, const int* in_sizes, int n_in,
                              void* d_out, int out_size)
{
    const float* stateH = (const float*)d_in[0];
    const float* stateK = (const float*)d_in[1];
    const float* W      = (const float*)d_in[2];
    const float* coeffs = (const float*)d_in[3];
    const float* omega  = (const float*)d_in[4];
    const int*   indK   = (const int*)  d_in[5];
    const int*   indHK  = (const int*)  d_in[6];
    const float* kK     = (const float*)d_in[7];
    const float* kH     = (const float*)d_in[8];
    float* out = (float*)d_out;

    int prLow, prHigh;
    cudaDeviceGetStreamPriorityRange(&prLow, &prHigh);
    cudaStream_t s2;
    cudaEvent_t evFork, evJoin;
    cudaStreamCreateWithPriority(&s2, cudaStreamNonBlocking, prHigh);
    cudaEventCreateWithFlags(&evFork, cudaEventDisableTiming);
    cudaEventCreateWithFlags(&evJoin, cudaEventDisableTiming);

    prep_kernel<<<1024, 256>>>(stateH, stateK, omega, out);

    cudaEventRecord(evFork, 0);
    cudaStreamWaitEvent(s2, evFork, 0);

    edge_kernel<<<32768, 256, 0, s2>>>(indK, indHK, W,   // high-prio stream
                                       coeffs, kK, kH, out);
    matvec_kernel<<<256, 256>>>(W, out);                 // default stream

    cudaEventRecord(evJoin, s2);
    cudaStreamWaitEvent(0, evJoin, 0);

    final_kernel<<<1024, 256>>>(out);
}

// round 15
// speedup vs baseline: 1.3423x; 1.3423x over previous
#include <cuda_runtime.h>
#include <cuda_fp16.h>
#include <cstdint>

#define N 8192
#define D 64
#define E 262144

// Scratch (no allocations allowed — __device__ globals)
__device__ float  g_sk[N * D];    // normalized state_K (fp32)
__device__ __half g_skh[N * D];   // normalized state_K (fp16, for edge gathers)
__device__ float  g_g[N];         // tanh(state_H)
__device__ float  g_fk[N * D];    // f_K accumulator (pre-projection)
__device__ float  g_zt[N];        // 0.5 * W_hop^T @ g accumulator
__device__ float  g_om[D * D];    // antisymmetrized (omega - omega^T)/2, ONCE

__device__ __forceinline__ void red_add_v4(float* p, float4 v) {
    asm volatile("red.global.add.v4.f32 [%0], {%1,%2,%3,%4};"
                 :: "l"(p), "f"(v.x), "f"(v.y), "f"(v.z), "f"(v.w)
                 : "memory");
}

// ---------------------------------------------------------------------------
// prep: sk = normalize(state_K rows) (fp32 + fp16), g = tanh(state_H),
//       zero accumulators, out_fH = -state_H.
//       Block 0 antisymmetrizes omega into g_om (transposed read paid ONCE).
// grid 1024 x 256 : one warp per row of state_K.
// ---------------------------------------------------------------------------
__global__ void __launch_bounds__(256) prep_kernel(
    const float* __restrict__ stateH,
    const float* __restrict__ stateK,
    const float* __restrict__ omega,
    float* __restrict__ outH)
{
    int tid  = threadIdx.x;
    int gtid = blockIdx.x * 256 + tid;

    ((float2*)g_fk)[gtid] = make_float2(0.f, 0.f);

    if (blockIdx.x == 0) {
        #pragma unroll
        for (int t = tid; t < D * D; t += 256) {
            int d = t >> 6, c = t & 63;
            g_om[t] = 0.5f * (omega[t] - omega[c * D + d]);
        }
    }

    int row  = gtid >> 5;
    int lane = tid & 31;
    float2 v = ((const float2*)(stateK + (size_t)row * D))[lane];
    float ss = v.x * v.x + v.y * v.y;
    #pragma unroll
    for (int o = 16; o; o >>= 1) ss += __shfl_xor_sync(0xffffffffu, ss, o);
    float inv = rsqrtf(ss);
    float2 s2 = make_float2(v.x * inv, v.y * inv);
    ((float2*)(g_sk + (size_t)row * D))[lane] = s2;
    ((__half2*)(g_skh + (size_t)row * D))[lane] = __float22half2_rn(s2);

    if (gtid < N) {
        float h = stateH[gtid];
        g_g[gtid]  = tanhf(h);
        g_zt[gtid] = 0.f;
        outH[gtid] = -h;
    }
}

// ---------------------------------------------------------------------------
// matvec: single pass over W_hop (256 MB) computing BOTH W@g and W^T@g.
// grid 256 x 256, 32 rows/block — half the co-resident blocks so the
// CONCURRENT edge kernel keeps occupancy; DRAM saturation preserved via MLP
// (8-deep float4 streams, ~2 waves). g_zt flush traffic also halves.
// ---------------------------------------------------------------------------
#define MV_ROWS 32

__global__ void __launch_bounds__(256) matvec_kernel(
    const float* __restrict__ W,
    float* __restrict__ outH)
{
    __shared__ float4 gsh[N / 4];
    int tid = threadIdx.x;
    #pragma unroll
    for (int k = 0; k < 8; k++)
        gsh[tid + 256 * k] = ((const float4*)g_g)[tid + 256 * k];
    __syncthreads();
    const float* gs = (const float*)gsh;

    float4 va[8];
    #pragma unroll
    for (int k = 0; k < 8; k++) va[k] = make_float4(0.f, 0.f, 0.f, 0.f);

    int r0 = blockIdx.x * MV_ROWS;
    for (int r = 0; r < MV_ROWS; r++) {
        const float4* rowp = (const float4*)(W + (size_t)(r0 + r) * N);
        float gr = gs[r0 + r];
        float dp = 0.f;
        #pragma unroll
        for (int k = 0; k < 8; k++) {
            float4 w  = __ldcs(&rowp[tid + 256 * k]);   // streaming, evict-first
            float4 gv = gsh[tid + 256 * k];
            dp = fmaf(w.x, gv.x, dp); dp = fmaf(w.y, gv.y, dp);
            dp = fmaf(w.z, gv.z, dp); dp = fmaf(w.w, gv.w, dp);
            va[k].x = fmaf(w.x, gr, va[k].x);
            va[k].y = fmaf(w.y, gr, va[k].y);
            va[k].z = fmaf(w.z, gr, va[k].z);
            va[k].w = fmaf(w.w, gr, va[k].w);
        }
        #pragma unroll
        for (int o = 16; o; o >>= 1) dp += __shfl_xor_sync(0xffffffffu, dp, o);
        if ((tid & 31) == 0) atomicAdd(&outH[r0 + r], 0.5f * dp);
    }
    #pragma unroll
    for (int k = 0; k < 8; k++) {
        int i4 = tid + 256 * k;
        red_add_v4(g_zt + 4 * i4,
                   make_float4(0.5f * va[k].x, 0.5f * va[k].y,
                               0.5f * va[k].z, 0.5f * va[k].w));
    }
}

// ---------------------------------------------------------------------------
// edges: both lists fused. Half-warp (16 lanes) per edge; fp16 sk gathers,
// fp32 math + red.v4 scatter. Measured 58.5us solo (LSU/REDG floor).
// grid 32768 x 256 (16 edges per block).
// ---------------------------------------------------------------------------
__global__ void __launch_bounds__(256) edge_kernel(
    const int* __restrict__ indK,
    const int* __restrict__ indHK,
    const float* __restrict__ W,
    const float* __restrict__ coeffs,
    const float* __restrict__ kKp,
    const float* __restrict__ kHp,
    float* __restrict__ outH)
{
    int gtid = blockIdx.x * 256 + threadIdx.x;
    int edge = gtid >> 4;               // half-warp id = edge id, [0, 2E)
    int l    = threadIdx.x & 15;

    bool isK = edge < E;
    int e2   = isK ? edge : edge - E;
    const int* ind = isK ? indK : indHK;
    int2 ij = ((const int2*)ind)[e2];
    int i = ij.x, j = ij.y;

    uint2 hi2 = ((const uint2*)(g_skh + (size_t)i * D))[l];
    uint2 hj2 = ((const uint2*)(g_skh + (size_t)j * D))[l];
    float2 a0 = __half22float2(*(const __half2*)&hi2.x);
    float2 a1 = __half22float2(*(const __half2*)&hi2.y);
    float2 b0 = __half22float2(*(const __half2*)&hj2.x);
    float2 b1 = __half22float2(*(const __half2*)&hj2.y);
    float4 si = make_float4(a0.x, a0.y, a1.x, a1.y);
    float4 sj = make_float4(b0.x, b0.y, b1.x, b1.y);

    float dp = si.x * sj.x + si.y * sj.y + si.z * sj.z + si.w * sj.w;
    #pragma unroll
    for (int o = 8; o; o >>= 1) dp += __shfl_xor_sync(0xffffffffu, dp, o, 16);

    float coef;
    if (isK) {
        float c0 = coeffs[0], c1 = coeffs[1], c2 = coeffs[2], c3 = coeffs[3];
        coef = dp * (c0 + dp * (c1 + dp * (c2 + dp * c3)));
    } else {
        float wij = 0.5f * (W[(size_t)i * N + j] + W[(size_t)j * N + i]);
        float gi = g_g[i], gj = g_g[j];
        if (l == 0) {
            float ikH = 1.f / *kHp;
            atomicAdd(&outH[i], dp * wij * gj * ikH);
            atomicAdd(&outH[j], dp * wij * gi * ikH);
        }
        coef = -gi * gj * wij / *kKp;
    }

    red_add_v4(g_fk + (size_t)i * D + 4 * l,
               make_float4(coef * sj.x, coef * sj.y, coef * sj.z, coef * sj.w));
    red_add_v4(g_fk + (size_t)j * D + 4 * l,
               make_float4(coef * si.x, coef * si.y, coef * si.z, coef * si.w));
}

// ---------------------------------------------------------------------------
// final: streaming combine + rotation (11.3us measured).
// grid 1024 x 256 (8 rows/block).
// ---------------------------------------------------------------------------
__global__ void __launch_bounds__(256, 3) final_kernel(float* __restrict__ out)
{
    __shared__ float Om[D * D];
    int tid  = threadIdx.x;
    int w    = tid >> 5;
    int lane = tid & 31;
    int r    = blockIdx.x * 8 + w;

    float2 raw = ((const float2*)(g_fk + (size_t)r * D))[lane];
    float2 skr = ((const float2*)(g_sk + (size_t)r * D))[lane];

    #pragma unroll
    for (int t = tid; t < D * D; t += 256)
        Om[t] = g_om[t];

    if (tid < 8) {
        int hidx = blockIdx.x * 8 + tid;
        out[hidx] += g_zt[hidx];
    }
    __syncthreads();

    float dp = skr.x * raw.x + skr.y * raw.y;
    #pragma unroll
    for (int o = 16; o; o >>= 1) dp += __shfl_xor_sync(0xffffffffu, dp, o);

    const float2* Om2 = (const float2*)Om;
    float ax = 0.f, ay = 0.f;
    #pragma unroll
    for (int dd = 0; dd < D; dd += 8) {
        float2 om[8];
        #pragma unroll
        for (int q = 0; q < 8; q++)
            om[q] = Om2[(dd + q) * 32 + lane];          // conflict-free LDS.64
        #pragma unroll
        for (int q = 0; q < 8; q++) {
            int d = dd + q;
            float s = __shfl_sync(0xffffffffu, (d & 1) ? skr.y : skr.x, d >> 1);
            ax = fmaf(s, om[q].x, ax);
            ay = fmaf(s, om[q].y, ay);
        }
    }

    float2 o2;
    o2.x = -raw.x + skr.x * dp + ax;
    o2.y = -raw.y + skr.y * dp + ay;
    ((float2*)(out + N))[r * 32 + lane] = o2;
}

// ---------------------------------------------------------------------------
// Launch graph (EXACT R13 structure — equal priority, matvec first):
//   prep ──┬── matvec (main stream, 256 blocks) ──┬── final
//          └── edge   (side stream, same prio)  ──┘
// R14 proved priority-high on a full-machine grid serializes; don't.
// ---------------------------------------------------------------------------
extern "C" void kernel_launch(void* const* d_in, const int* in_sizes, int n_in,
                              void* d_out, int out_size)
{
    const float* stateH = (const float*)d_in[0];
    const float* stateK = (const float*)d_in[1];
    const float* W      = (const float*)d_in[2];
    const float* coeffs = (const float*)d_in[3];
    const float* omega  = (const float*)d_in[4];
    const int*   indK   = (const int*)  d_in[5];
    const int*   indHK  = (const int*)  d_in[6];
    const float* kK     = (const float*)d_in[7];
    const float* kH     = (const float*)d_in[8];
    float* out = (float*)d_out;

    cudaStream_t s2;
    cudaEvent_t evFork, evJoin;
    cudaStreamCreateWithFlags(&s2, cudaStreamNonBlocking);
    cudaEventCreateWithFlags(&evFork, cudaEventDisableTiming);
    cudaEventCreateWithFlags(&evJoin, cudaEventDisableTiming);

    prep_kernel<<<1024, 256>>>(stateH, stateK, omega, out);

    cudaEventRecord(evFork, 0);
    cudaStreamWaitEvent(s2, evFork, 0);

    matvec_kernel<<<256, 256>>>(W, out);                 // main stream
    edge_kernel<<<32768, 256, 0, s2>>>(indK, indHK, W,   // side stream
                                       coeffs, kK, kH, out);

    cudaEventRecord(evJoin, s2);
    cudaStreamWaitEvent(0, evJoin, 0);

    final_kernel<<<1024, 256>>>(out);
}